// round 16
// baseline (speedup 1.0000x reference)
#include <cuda_runtime.h>
#include <cuda_fp16.h>

#define NN 2048
#define LOG2F_ 0.69314718055994530942f

typedef unsigned long long ull;

// Scratch (__device__ globals; no cudaMalloc allowed)
// fp16 2-term split rows: [n][0..31]=hi, [n][32..63]=mid (128B rows).
// Concatenated K=64 fp16 GEMM gives hi.hi + mid.mid; missing cross terms
// ~2^-12 |u| (vs 2^-9 for bf16 -> measured 6.4e-4 there => ~8e-5 here).
// Diagonal u_ii is computed EXACTLY in fp32 at finalize time.
__device__ __align__(16) __half g_Af16[NN * 64];  // M2 (i side / MMA A)
__device__ __align__(16) __half g_Bf16[NN * 64];  // M1 (j side / MMA B)
__device__ __align__(16) float g_M2f[NN * 32];    // M2 fp32 (exact diag)
__device__ __align__(16) float g_M1f[NN * 32];    // M1 fp32 (exact diag)
__device__ float g_partial[16 * NN];  // [jtile][row] softplus row sums
__device__ unsigned g_ticket = 0;     // last-block ticket (monotone, %256)

// ---- packed f32x2 helpers ----
__device__ __forceinline__ ull pack2(float x, float y) {
    ull r;
    asm("mov.b64 %0, {%1, %2};" : "=l"(r) : "r"(__float_as_uint(x)), "r"(__float_as_uint(y)));
    return r;
}
__device__ __forceinline__ void unpack2(ull v, float& x, float& y) {
    unsigned lo, hi;
    asm("mov.b64 {%0, %1}, %2;" : "=r"(lo), "=r"(hi) : "l"(v));
    x = __uint_as_float(lo); y = __uint_as_float(hi);
}
__device__ __forceinline__ ull ffma2(ull a, ull b, ull c) {
    ull d;
    asm("fma.rn.f32x2 %0, %1, %2, %3;" : "=l"(d) : "l"(a), "l"(b), "l"(c));
    return d;
}
__device__ __forceinline__ float softplus_f(float x) {
    float a = fabsf(x);
    float l = __logf(1.f + __expf(-a));
    return fmaxf(x, 0.f) + l;
}

// warp-level fp16 tensor-core mma: D(16x8,f32) += A(16x16,f16) x B(16x8,f16)
__device__ __forceinline__ void mma16816(float* c, const unsigned* a,
                                         const unsigned* b) {
    asm volatile(
        "mma.sync.aligned.m16n8k16.row.col.f32.f16.f16.f32 "
        "{%0,%1,%2,%3}, {%4,%5,%6,%7}, {%8,%9}, {%0,%1,%2,%3};"
        : "+f"(c[0]), "+f"(c[1]), "+f"(c[2]), "+f"(c[3])
        : "r"(a[0]), "r"(a[1]), "r"(a[2]), "r"(a[3]), "r"(b[0]), "r"(b[1]));
}

// ---- embed smem layout (static 45.3KB, aliased regions) ----
#define SM_IN    0
#define SM_SP1   10240
#define SM_SP2   26624
#define SM_PART  34816
#define SM_SB1   45056
#define SM_SB2   45184
#define SM_TOTAL 45312

// ---------------------------------------------------------------------------
// Kernel 1 (v5 + fp16 2-term emit + fp32 emit): embeddings + leaky_relu +
// agent-mean. Compute identical to R10; emit = fp16 [h|m] rows for the MMA
// plus fp32 rows for the exact-diagonal finalize.
// ---------------------------------------------------------------------------
__global__ void __launch_bounds__(256) embed_kernel(
    const float* __restrict__ state, const float* __restrict__ action,
    const float* __restrict__ W1, const float* __restrict__ b1,
    const float* __restrict__ W2, const float* __restrict__ b2) {
    __shared__ __align__(16) char smem[SM_TOTAL];
    float* sIN = (float*)(smem + SM_IN);
    ull   (*sP1)[32] = (ull (*)[32])(smem + SM_SP1);
    ull   (*sP2)[32] = (ull (*)[32])(smem + SM_SP2);
    float (*spart)[4][5][32] = (float (*)[4][5][32])(smem + SM_PART);
    float* sb1 = (float*)(smem + SM_SB1);
    float* sb2 = (float*)(smem + SM_SB2);

    const int tid = threadIdx.x;

    #pragma unroll
    for (int i = 0; i < 8; i++) {
        int idx = tid + i * 256;
        int k2 = idx >> 5, u = idx & 31;
        sP1[k2][u] = pack2(W1[k2 * 64 + u], W1[k2 * 64 + 32 + u]);
    }
    #pragma unroll
    for (int i = 0; i < 4; i++) {
        int idx = tid + i * 256;
        int k2 = idx >> 5, u = idx & 31;
        sP2[k2][u] = pack2(W2[k2 * 64 + u], W2[k2 * 64 + 32 + u]);
    }
    {   // stage state tile: 4 samples x 640 floats, coalesced
        const float4* sg = (const float4*)(state + (size_t)blockIdx.x * 2560);
        float4* si4 = (float4*)sIN;
        si4[tid]       = sg[tid];
        si4[tid + 256] = sg[tid + 256];
        if (tid < 128) si4[tid + 512] = sg[tid + 512];
    }
    if (tid < 32) { sb1[tid] = b1[tid]; sb2[tid] = b2[tid]; }
    __syncthreads();

    const int nl = tid >> 6, kq = (tid >> 4) & 3, uh = tid & 15;
    const int n8 = blockIdx.x * 4;

    // ---------------- GEMM1: state @ W1, K-quarter (32 of 128) ------------
    {
        const float* base = sIN + nl * 640 + kq * 32;
        ull acc[5][2];
        #pragma unroll
        for (int a = 0; a < 5; a++) { acc[a][0] = 0ull; acc[a][1] = 0ull; }

        #pragma unroll
        for (int k4 = 0; k4 < 8; k4++) {
            ulonglong2 x[5];
            #pragma unroll
            for (int a = 0; a < 5; a++)
                x[a] = *(const ulonglong2*)(base + a * 128 + k4 * 4);
            const int k2 = kq * 16 + k4 * 2;
            ulonglong2 w0 = *(const ulonglong2*)&sP1[k2][2 * uh];
            ulonglong2 w1 = *(const ulonglong2*)&sP1[k2 + 1][2 * uh];
            #pragma unroll
            for (int a = 0; a < 5; a++) {
                acc[a][0] = ffma2(x[a].x, w0.x, acc[a][0]);
                acc[a][0] = ffma2(x[a].y, w1.x, acc[a][0]);
                acc[a][1] = ffma2(x[a].x, w0.y, acc[a][1]);
                acc[a][1] = ffma2(x[a].y, w1.y, acc[a][1]);
            }
        }
        #pragma unroll
        for (int a = 0; a < 5; a++) {
            float x0, x1, y0, y1;
            unpack2(acc[a][0], x0, x1);
            unpack2(acc[a][1], y0, y1);
            *(float2*)&spart[nl][kq][a][2 * uh] = make_float2(x0 + x1, y0 + y1);
        }
    }
    __syncthreads();

    // finalize1 (threads 0..127) + restage action (threads 128..255)
    if (tid < 128) {
        const int fu = tid >> 2, fnl = tid & 3;
        const int fn = n8 + fnl;
        float m = 0.f;
        #pragma unroll
        for (int a = 0; a < 5; a++) {
            float v = sb1[fu];
            #pragma unroll
            for (int q = 0; q < 4; q++) v += spart[fnl][q][a][fu];
            m += (v > 0.f) ? v : 0.01f * v;          // leaky_relu(0.01)
        }
        float v1 = 0.2f * m;
        __half h = __float2half_rn(v1);
        g_Bf16[fn * 64 + fu]      = h;
        g_Bf16[fn * 64 + 32 + fu] = __float2half_rn(v1 - __half2float(h));
        g_M1f[fn * 32 + fu]       = v1;              // exact for diag
    } else {
        const int t = tid - 128;
        const float4* ag = (const float4*)(action + (size_t)blockIdx.x * 1280);
        float4* si4 = (float4*)sIN;
        si4[t]       = ag[t];
        si4[t + 128] = ag[t + 128];
        if (t < 64) si4[t + 256] = ag[t + 256];
    }
    __syncthreads();

    // ---------------- GEMM2: action @ W2, K-quarter (16 of 64) ------------
    {
        const float* base = sIN + nl * 320 + kq * 16;
        ull acc[5][2];
        #pragma unroll
        for (int a = 0; a < 5; a++) { acc[a][0] = 0ull; acc[a][1] = 0ull; }

        #pragma unroll
        for (int k4 = 0; k4 < 4; k4++) {
            ulonglong2 x[5];
            #pragma unroll
            for (int a = 0; a < 5; a++)
                x[a] = *(const ulonglong2*)(base + a * 64 + k4 * 4);
            const int k2 = kq * 8 + k4 * 2;
            ulonglong2 w0 = *(const ulonglong2*)&sP2[k2][2 * uh];
            ulonglong2 w1 = *(const ulonglong2*)&sP2[k2 + 1][2 * uh];
            #pragma unroll
            for (int a = 0; a < 5; a++) {
                acc[a][0] = ffma2(x[a].x, w0.x, acc[a][0]);
                acc[a][0] = ffma2(x[a].y, w1.x, acc[a][0]);
                acc[a][1] = ffma2(x[a].x, w0.y, acc[a][1]);
                acc[a][1] = ffma2(x[a].y, w1.y, acc[a][1]);
            }
        }
        __syncthreads();
        #pragma unroll
        for (int a = 0; a < 5; a++) {
            float x0, x1, y0, y1;
            unpack2(acc[a][0], x0, x1);
            unpack2(acc[a][1], y0, y1);
            *(float2*)&spart[nl][kq][a][2 * uh] = make_float2(x0 + x1, y0 + y1);
        }
    }
    __syncthreads();

    if (tid < 128) {
        const int fu = tid >> 2, fnl = tid & 3;
        const int fn = n8 + fnl;
        float m = 0.f;
        #pragma unroll
        for (int a = 0; a < 5; a++) {
            float v = sb2[fu];
            #pragma unroll
            for (int q = 0; q < 4; q++) v += spart[fnl][q][a][fu];
            m += (v > 0.f) ? v : 0.01f * v;
        }
        float v2 = 0.2f * m;
        __half h = __float2half_rn(v2);
        g_Af16[fn * 64 + fu]      = h;
        g_Af16[fn * 64 + 32 + fu] = __float2half_rn(v2 - __half2float(h));
        g_M2f[fn * 32 + fu]       = v2;              // exact for diag
    }
}

// ---------------------------------------------------------------------------
// Kernel 2 (v10, fp16 mma.sync, K=64 concat): u ~= hi.hi + mid.mid.
// R13's measured-best structure verbatim (grid 256 = 16x16 tiles of 128x128;
// warp = 16 rows x 128 cols; 4 ksteps x 16 nb = 64 MMAs/warp; scalar
// fragment LDS, TSTRIDE=144 conflict-free). No diag capture in the hot path:
// the last-block finalize recomputes u_ii exactly in fp32.
// Epilogue: batched softplus (prod of 32 factors <= 2^32), quad shfl-reduce,
// last-block ticket finalize.
// ---------------------------------------------------------------------------
#define TSTRIDE 144
__global__ void __launch_bounds__(256) jsd_kernel(float* __restrict__ out) {
    __shared__ __align__(16) char sA[128 * TSTRIDE];   // 18 KB
    __shared__ __align__(16) char sB[128 * TSTRIDE];   // 18 KB
    __shared__ unsigned s_last;

    const int tid = threadIdx.x;
    const int w = tid >> 5, lane = tid & 31;
    const int ib = blockIdx.x >> 4, q = blockIdx.x & 15;
    const int i0 = ib * 128, j0 = q * 128;

    // stage tiles: 128B rows = 8 x 16B granules
    #pragma unroll
    for (int t = 0; t < 4; t++) {
        int idx = tid + t * 256;                     // 0..1023
        int row = idx >> 3, g = idx & 7;
        *(uint4*)(sA + row * TSTRIDE + g * 16) =
            *(const uint4*)&g_Af16[(i0 + row) * 64 + g * 8];
        *(uint4*)(sB + row * TSTRIDE + g * 16) =
            *(const uint4*)&g_Bf16[(j0 + row) * 64 + g * 8];
    }
    __syncthreads();

    // accumulators: 16 nblocks x {c0,c1 (row rA), c2,c3 (row rA+8)}
    float acc[16][4];
    #pragma unroll
    for (int nb = 0; nb < 16; nb++)
        #pragma unroll
        for (int p = 0; p < 4; p++) acc[nb][p] = 0.f;

    const int grp = lane >> 2, four = lane & 3;      // fragment coords
    const char* arow0 = sA + (w * 16 + grp) * TSTRIDE + four * 4;
    const char* brow0 = sB + grp * TSTRIDE + four * 4;

    #pragma unroll
    for (int ks = 0; ks < 4; ks++) {                 // K = 4 x 16 (concat h|m)
        const int kb = ks * 32;                      // byte offset of kstep
        unsigned afr[4];
        afr[0] = *(const unsigned*)(arow0 + kb);               // row grp,   k lo-half
        afr[1] = *(const unsigned*)(arow0 + 8 * TSTRIDE + kb); // row grp+8
        afr[2] = *(const unsigned*)(arow0 + kb + 16);          // k hi-half
        afr[3] = *(const unsigned*)(arow0 + 8 * TSTRIDE + kb + 16);
        #pragma unroll
        for (int nb = 0; nb < 16; nb++) {
            unsigned bfr[2];
            const char* bp = brow0 + nb * 8 * TSTRIDE + kb;
            bfr[0] = *(const unsigned*)(bp);                   // k lo-half, col grp
            bfr[1] = *(const unsigned*)(bp + 16);              // k hi-half
            mma16816(acc[nb], afr, bfr);
        }
    }

    // epilogue: rows rA (c0,c1) and rA+8 (c2,c3); batched softplus
    const int rA = i0 + w * 16 + grp;
    const int rB = rA + 8;
    float linA = 0.f, prodA = 1.f, linB = 0.f, prodB = 1.f;
    #pragma unroll
    for (int nb = 0; nb < 16; nb++) {
        float c0 = acc[nb][0], c1 = acc[nb][1];
        float c2 = acc[nb][2], c3 = acc[nb][3];
        linA  += fmaxf(c0, 0.f) + fmaxf(c1, 0.f);
        prodA *= (1.f + __expf(-fabsf(c0))) * (1.f + __expf(-fabsf(c1)));
        linB  += fmaxf(c2, 0.f) + fmaxf(c3, 0.f);
        prodB *= (1.f + __expf(-fabsf(c2))) * (1.f + __expf(-fabsf(c3)));
    }
    float sAr = linA + __logf(prodA);                // 32 softplus, 1 log
    float sBr = linB + __logf(prodB);

    // reduce across the 4 lanes of the quad sharing each row
    sAr += __shfl_xor_sync(0xffffffffu, sAr, 1);
    sAr += __shfl_xor_sync(0xffffffffu, sAr, 2);
    sBr += __shfl_xor_sync(0xffffffffu, sBr, 1);
    sBr += __shfl_xor_sync(0xffffffffu, sBr, 2);
    if (four == 0) {
        g_partial[q * NN + rA] = sAr;
        g_partial[q * NN + rB] = sBr;
    }

    // ---- last-block finalize (threadFenceReduction pattern) ----
    __threadfence();                                 // publish partials
    __syncthreads();
    if (tid == 0) {
        unsigned old = atomicAdd(&g_ticket, 1u);
        s_last = ((old & 255u) == 255u) ? 1u : 0u;   // grid == 256 exactly
    }
    __syncthreads();
    if (s_last) {
        __threadfence();                             // acquire others' writes
        #pragma unroll
        for (int r = 0; r < 8; r++) {
            const int i = tid + r * 256;
            float tot = 0.f;
            #pragma unroll
            for (int p = 0; p < 16; p++) tot += g_partial[p * NN + i];

            // exact fp32 diagonal: u_ii = M2[i] . M1[i]
            float ud = 0.f;
            const float4* a4 = (const float4*)&g_M2f[i * 32];
            const float4* b4 = (const float4*)&g_M1f[i * 32];
            #pragma unroll
            for (int u4 = 0; u4 < 8; u4++) {
                float4 av = a4[u4], bv = b4[u4];
                ud += av.x * bv.x + av.y * bv.y + av.z * bv.z + av.w * bv.w;
            }

            float spd = softplus_f(ud);
            float Eneg = (tot - spd - 2047.f * LOG2F_) * (1.f / 2047.f);
            float Epos = LOG2F_ - spd + ud;          // = log2 - softplus(-u_ii)
            out[i]      = Eneg - Epos;               // loss
            out[NN + i] = Epos;                      // MI
        }
    }
}

extern "C" void kernel_launch(void* const* d_in, const int* in_sizes, int n_in,
                              void* d_out, int out_size) {
    const float* state  = (const float*)d_in[0];
    const float* action = (const float*)d_in[1];
    const float* W1     = (const float*)d_in[2];
    const float* b1     = (const float*)d_in[3];
    const float* W2     = (const float*)d_in[4];
    const float* b2     = (const float*)d_in[5];
    float* out = (float*)d_out;

    embed_kernel<<<NN / 4, 256>>>(state, action, W1, b1, W2, b2);
    jsd_kernel<<<256, 256>>>(out);
}